// round 6
// baseline (speedup 1.0000x reference)
#include <cuda_runtime.h>
#include <math.h>
#include <stdint.h>

// ---------------- problem constants ----------------
#define DDIM 512
#define TSTEPS 1024
#define BATCH 8
#define NSLOT 32
#define CPB 16            // CTAs per batch == cluster size
#define SLICE 32          // d-slice per CTA
#define MROWS (BATCH*TSTEPS)
#define SCAN_THREADS 512

// ---------------- static device scratch ----------------
__device__ float g_xproj[(size_t)MROWS * DDIM];
__device__ float g_siluz[(size_t)MROWS * DDIM];
__device__ float g_xw   [(size_t)MROWS * DDIM];
__device__ float g_hs   [(size_t)MROWS * DDIM];

__device__ __forceinline__ float siluf(float v) { return v / (1.0f + __expf(-v)); }

// ---------------- cluster / mbarrier helpers ----------------
__device__ __forceinline__ uint32_t smem_u32(const void* p) {
    return (uint32_t)__cvta_generic_to_shared(p);
}
__device__ __forceinline__ void mbar_init(uint32_t a, uint32_t cnt) {
    asm volatile("mbarrier.init.shared.b64 [%0], %1;" :: "r"(a), "r"(cnt) : "memory");
}
__device__ __forceinline__ uint32_t mapa_u32(uint32_t a, uint32_t rank) {
    uint32_t r;
    asm volatile("mapa.shared::cluster.u32 %0, %1, %2;" : "=r"(r) : "r"(a), "r"(rank));
    return r;
}
// cluster-scope RELEASE arrive: publishes (cumulatively, post-__syncthreads)
// all CTA stores to the peer that acquires on this barrier.
__device__ __forceinline__ void mbar_arrive_cluster(uint32_t a) {
    asm volatile("mbarrier.arrive.release.cluster.shared::cluster.b64 _, [%0];"
                 :: "r"(a) : "memory");
}
__device__ __forceinline__ void st_cluster_f4(uint32_t addr, float4 v) {
    asm volatile("st.shared::cluster.v4.f32 [%0], {%1,%2,%3,%4};"
                 :: "r"(addr), "f"(v.x), "f"(v.y), "f"(v.z), "f"(v.w) : "memory");
}
__device__ __forceinline__ void mbar_wait(uint32_t a, uint32_t parity) {
    asm volatile(
        "{\n\t"
        ".reg .pred P1;\n\t"
        "WAITLOOP%=:\n\t"
        "mbarrier.try_wait.parity.acquire.cluster.shared::cta.b64 P1, [%0], %1, 0x989680;\n\t"
        "@P1 bra WAITDONE%=;\n\t"
        "bra WAITLOOP%=;\n\t"
        "WAITDONE%=:\n\t"
        "}"
        :: "r"(a), "r"(parity) : "memory");
}
__device__ __forceinline__ void cluster_sync_all() {
    asm volatile("barrier.cluster.arrive.aligned;" ::: "memory");
    asm volatile("barrier.cluster.wait.aligned;" ::: "memory");
}
__device__ __forceinline__ uint32_t my_ctarank() {
    uint32_t r;
    asm("mov.u32 %0, %%cluster_ctarank;" : "=r"(r));
    return r;
}

// ---------------- exact 1.5-entmax over 32 values, one per lane ----------------
// Sort-free: rank by all-pairs broadcast (ties by lane index), then rank-gated
// prefix sums. Identical closed form to the reference; cumsums are
// permutation-invariant over ties.
__device__ __forceinline__ float entmax15_warp(float z, int lane) {
    const unsigned F = 0xffffffffu;
    float x0 = 0.5f * z;
    // rank (descending, ties broken by lower lane first) — 32 independent shfls
    int rank = 0;
#pragma unroll
    for (int j = 0; j < 32; j++) {
        float xj = __shfl_sync(F, x0, j);
        rank += (xj > x0 || (xj == x0 && j < lane)) ? 1 : 0;
    }
    // max reduce (overlaps with rank pass; ranks are shift-invariant)
    float m = x0;
#pragma unroll
    for (int o = 16; o > 0; o >>= 1) m = fmaxf(m, __shfl_xor_sync(F, m, o));
    float x = x0 - m;
    // lane k accumulates sum/sumsq of the top-(k+1) values; zsv = sorted value at k
    float s = 0.f, s2 = 0.f, zsv = 0.f;
#pragma unroll
    for (int j = 0; j < 32; j++) {
        float xj = __shfl_sync(F, x, j);
        int   rj = __shfl_sync(F, rank, j);
        if (rj <= lane) { s += xj; s2 += xj * xj; }
        if (rj == lane) zsv = xj;
    }
    float k1     = (float)(lane + 1);
    float mean   = s / k1;
    float meansq = s2 / k1;
    float ss     = k1 * (meansq - mean * mean);
    float delta  = (1.0f - ss) / k1;
    float tau    = mean - sqrtf(fmaxf(delta, 0.0f));
    unsigned bal = __ballot_sync(F, tau <= zsv);
    int support  = __popc(bal) - 1;
    float tau_star = __shfl_sync(F, tau, support);
    float p = fmaxf(x - tau_star, 0.0f);
    return p * p;
}

// ---------------- SGEMM: C[M,N] = A[M,K] @ B[N,K]^T (unchanged, passing) ----------------
template <int MODE>
__global__ void __launch_bounds__(256)
sgemm(const float* __restrict__ Aext, const float* __restrict__ Bmat,
      float* __restrict__ Cout, int M, int N, int K)
{
    __shared__ float As[8 * 128];
    __shared__ float Bs[8 * 128];

    const int tid = threadIdx.x;
    const int bm = blockIdx.y * 128;
    const int bn = blockIdx.x * 128;
    const int lrow = tid >> 1;
    const int lk   = (tid & 1) * 4;
    const int tx = tid & 15;
    const int ty = tid >> 4;

    const float* A = (MODE == 0) ? Aext : ((MODE == 1) ? g_xproj : g_hs);

    float acc[8][8];
#pragma unroll
    for (int i = 0; i < 8; i++)
#pragma unroll
        for (int j = 0; j < 8; j++) acc[i][j] = 0.0f;

    for (int kt = 0; kt < K; kt += 8) {
        float4 av = *(const float4*)(A + (size_t)(bm + lrow) * K + kt + lk);
        if (MODE == 2) {
            float4 sv = *(const float4*)(g_siluz + (size_t)(bm + lrow) * K + kt + lk);
            av.x *= sv.x; av.y *= sv.y; av.z *= sv.z; av.w *= sv.w;
        }
        As[(lk + 0) * 128 + lrow] = av.x;
        As[(lk + 1) * 128 + lrow] = av.y;
        As[(lk + 2) * 128 + lrow] = av.z;
        As[(lk + 3) * 128 + lrow] = av.w;
        float4 bv = *(const float4*)(Bmat + (size_t)(bn + lrow) * K + kt + lk);
        Bs[(lk + 0) * 128 + lrow] = bv.x;
        Bs[(lk + 1) * 128 + lrow] = bv.y;
        Bs[(lk + 2) * 128 + lrow] = bv.z;
        Bs[(lk + 3) * 128 + lrow] = bv.w;
        __syncthreads();
#pragma unroll
        for (int kk = 0; kk < 8; kk++) {
            float af[8], bf[8];
            *(float4*)(af + 0) = *(const float4*)(As + kk * 128 + ty * 8 + 0);
            *(float4*)(af + 4) = *(const float4*)(As + kk * 128 + ty * 8 + 4);
            *(float4*)(bf + 0) = *(const float4*)(Bs + kk * 128 + tx * 8 + 0);
            *(float4*)(bf + 4) = *(const float4*)(Bs + kk * 128 + tx * 8 + 4);
#pragma unroll
            for (int i = 0; i < 8; i++)
#pragma unroll
                for (int j = 0; j < 8; j++)
                    acc[i][j] = fmaf(af[i], bf[j], acc[i][j]);
        }
        __syncthreads();
    }

#pragma unroll
    for (int i = 0; i < 8; i++) {
        const size_t m = (size_t)(bm + ty * 8 + i);
#pragma unroll
        for (int j = 0; j < 8; j++) {
            const int gn = bn + tx * 8 + j;
            float v = acc[i][j];
            if (MODE == 0) {
                if (gn < DDIM) g_xproj[m * DDIM + gn] = siluf(v);
                else           g_siluz[m * DDIM + (gn - DDIM)] = siluf(v);
            } else if (MODE == 1) {
                g_xw[m * DDIM + gn] = v;
            } else {
                Cout[m * DDIM + gn] = v;
            }
        }
    }
}

// ---------------- shared-memory layout (float offsets) ----------------
#define RBUF_F 4      // [CPB][32]  r-score partials
#define EX2_F  516    // [CPB][64]  h_new slice (0:32) + w partials (32:64)
#define TAPE_F 1540   // [32][33]
#define WORK_F 2596   // [512]
#define HPRE_F 3108   // [32]
#define HNEW_F 3140   // [32]
#define BV_F   3172   // [32]
#define WVAL_F 3204   // [32]
#define RPS_F  3236   // [32]
#define SRC_F  3268   // [64] staging for phase-B send
#define WW_F   3332   // [32*512]  W_write slice (W_h lives in registers)
#define SCAN_SMEM_F (WW_F + SLICE*DDIM)

// ---------------- dual-memory scan: 16-CTA cluster per batch ----------------
__global__ void __cluster_dims__(CPB, 1, 1) __launch_bounds__(SCAN_THREADS, 1)
scan_kernel(const float* __restrict__ W_h, const float* __restrict__ W_write,
            const float* __restrict__ b_h, float* __restrict__ dout)
{
    extern __shared__ float sm[];
    float* rbuf   = sm + RBUF_F;
    float* ex2    = sm + EX2_F;
    float* tape_s = sm + TAPE_F;
    float* work_s = sm + WORK_F;
    float* hpre_s = sm + HPRE_F;
    float* hnew_s = sm + HNEW_F;
    float* bv_s   = sm + BV_F;
    float* wval_s = sm + WVAL_F;
    float* rp_s   = sm + RPS_F;
    float* src64  = sm + SRC_F;
    float* Ww_s   = sm + WW_F;

    const int tid  = threadIdx.x;
    const int wid  = tid >> 5;
    const int lane = tid & 31;
    const uint32_t c = my_ctarank();            // 0..15 within cluster
    const int b      = blockIdx.x / CPB;        // batch
    const int dbase  = (int)c * SLICE;
    const float scale = 0.044194173824159216f;  // 1/sqrt(512)
    const unsigned F = 0xffffffffu;
    const int o0 = 2 * wid, o1 = o0 + 1;

    const uint32_t smb  = smem_u32(sm);
    const uint32_t bar0 = smb;
    const uint32_t bar1 = smb + 8;
    const uint32_t rbuf_u = smb + RBUF_F * 4;
    const uint32_t ex2_u  = smb + EX2_F * 4;

    if (tid == 0) {
        mbar_init(bar0, CPB);   // ONE arrive per source CTA
        mbar_init(bar1, CPB);
    }
    // W_write slice in SMEM
    for (int i = tid; i < SLICE * DDIM / 4; i += SCAN_THREADS)
        ((float4*)Ww_s)[i] = ((const float4*)(W_write + (size_t)dbase * DDIM))[i];
    // W_h rows o0/o1 in registers: wh[kk] = W_h[o0][lane+32kk], wh[16+kk] = W_h[o1][...]
    float wh[32];
#pragma unroll
    for (int kk = 0; kk < 16; kk++) {
        wh[kk]      = W_h[(size_t)(dbase + o0) * DDIM + lane + kk * 32];
        wh[16 + kk] = W_h[(size_t)(dbase + o1) * DDIM + lane + kk * 32];
    }
    for (int i = tid; i < NSLOT * 33; i += SCAN_THREADS) tape_s[i] = 0.0f;
    for (int i = tid; i < DDIM; i += SCAN_THREADS) work_s[i] = 0.0f;
    __syncthreads();
    cluster_sync_all();

    float bh0 = 0.f, bh1 = 0.f, xw0 = 0.f, xw1 = 0.f;
    if (lane == 0) {
        bh0 = b_h[dbase + o0];
        bh1 = b_h[dbase + o1];
        size_t off0 = ((size_t)b * TSTEPS) * DDIM + dbase;
        xw0 = g_xw[off0 + o0];
        xw1 = g_xw[off0 + o1];
    }

    for (int t = 0; t < TSTEPS; t++) {
        const uint32_t parity = (uint32_t)(t & 1);

        // ---- Phase A: h_pre slice (W_h from registers) ----
        {
            float acc0 = 0.0f, acc1 = 0.0f;
#pragma unroll
            for (int kk = 0; kk < 16; kk++) {
                float wv = work_s[lane + kk * 32];
                acc0 = fmaf(wh[kk],      wv, acc0);
                acc1 = fmaf(wh[16 + kk], wv, acc1);
            }
#pragma unroll
            for (int o = 16; o > 0; o >>= 1) {
                acc0 += __shfl_xor_sync(F, acc0, o);
                acc1 += __shfl_xor_sync(F, acc1, o);
            }
            if (lane == 0) {
                hpre_s[o0] = acc0 + xw0 + bh0;
                hpre_s[o1] = acc1 + xw1 + bh1;
            }
        }
        __syncthreads();
        // r partials over local d-slice
        {
            float hp = hpre_s[lane];
            float rp0 = tape_s[o0 * 33 + lane] * hp;
            float rp1 = tape_s[o1 * 33 + lane] * hp;
#pragma unroll
            for (int o = 16; o > 0; o >>= 1) {
                rp0 += __shfl_xor_sync(F, rp0, o);
                rp1 += __shfl_xor_sync(F, rp1, o);
            }
            if (lane == 0) { rp_s[o0] = rp0; rp_s[o1] = rp1; }
        }
        __syncthreads();
        // warp0 lanes 0..15: each ships the whole staged slice to one peer,
        // then one release-arrive (16 arrives per barrier total)
        if (tid < CPB) {
            uint32_t dst = mapa_u32(rbuf_u + (uint32_t)c * 32u * 4u, (uint32_t)tid);
#pragma unroll
            for (int q = 0; q < 8; q++) st_cluster_f4(dst + q * 16, ((const float4*)rp_s)[q]);
            mbar_arrive_cluster(mapa_u32(bar0, (uint32_t)tid));
        }
        if (wid == 0) mbar_wait(bar0, parity);

        // ---- Phase B: warp0 reduces r, entmax(a), read, h_new ----
        if (wid == 0) {
            float rs = 0.0f;
#pragma unroll
            for (int s = 0; s < CPB; s++) rs += rbuf[s * 32 + lane];
            rs *= scale;
            float a = entmax15_warp(rs, lane);
            float rd = 0.0f;
#pragma unroll
            for (int n = 0; n < NSLOT; n++)
                rd = fmaf(__shfl_sync(F, a, n), tape_s[n * 33 + lane], rd);
            float hn = tanhf(hpre_s[lane] + rd);
            hnew_s[lane] = hn;
            src64[lane] = hn;
        }
        __syncthreads();   // propagates warp0's acquire + h_new to all warps
        {
            float hv = hnew_s[lane];
            float wp0 = tape_s[o0 * 33 + lane] * hv;
            float wp1 = tape_s[o1 * 33 + lane] * hv;
#pragma unroll
            for (int o = 16; o > 0; o >>= 1) {
                wp0 += __shfl_xor_sync(F, wp0, o);
                wp1 += __shfl_xor_sync(F, wp1, o);
            }
            if (lane == 0) { src64[32 + o0] = wp0; src64[32 + o1] = wp1; }
        }
        __syncthreads();
        if (tid < CPB) {
            uint32_t dst = mapa_u32(ex2_u + (uint32_t)c * 64u * 4u, (uint32_t)tid);
#pragma unroll
            for (int q = 0; q < 16; q++) st_cluster_f4(dst + q * 16, ((const float4*)src64)[q]);
            mbar_arrive_cluster(mapa_u32(bar1, (uint32_t)tid));
        }
        if (wid == 0) mbar_wait(bar1, parity);
        __syncthreads();   // propagate acquire before all warps read ex2

        // ---- Phase C: gather h, entmax(b) || w_val matvec, tape update ----
        work_s[tid] = ex2[wid * 64 + lane];       // full h_new assembled
        if (lane == 0 && t + 1 < TSTEPS) {        // prefetch next xw
            size_t offn = ((size_t)b * TSTEPS + (t + 1)) * DDIM + dbase;
            xw0 = g_xw[offn + o0];
            xw1 = g_xw[offn + o1];
        }
        __syncthreads();
        if (wid == 0) {
            float ws = 0.0f;
#pragma unroll
            for (int s = 0; s < CPB; s++) ws += ex2[s * 64 + 32 + lane];
            ws *= scale;
            bv_s[lane] = entmax15_warp(ws, lane);
        } else if (wid >= 8) {
            int r0 = (wid - 8) * 4;
            float a0 = 0.f, a1 = 0.f, a2 = 0.f, a3 = 0.f;
            const float* w0 = Ww_s + (r0 + 0) * DDIM;
            const float* w1 = Ww_s + (r0 + 1) * DDIM;
            const float* w2 = Ww_s + (r0 + 2) * DDIM;
            const float* w3 = Ww_s + (r0 + 3) * DDIM;
#pragma unroll
            for (int kk = 0; kk < 16; kk++) {
                int d = lane + kk * 32;
                float hv = work_s[d];
                a0 = fmaf(w0[d], hv, a0);
                a1 = fmaf(w1[d], hv, a1);
                a2 = fmaf(w2[d], hv, a2);
                a3 = fmaf(w3[d], hv, a3);
            }
#pragma unroll
            for (int o = 16; o > 0; o >>= 1) {
                a0 += __shfl_xor_sync(F, a0, o);
                a1 += __shfl_xor_sync(F, a1, o);
                a2 += __shfl_xor_sync(F, a2, o);
                a3 += __shfl_xor_sync(F, a3, o);
            }
            if (lane == 0) {
                wval_s[r0 + 0] = a0; wval_s[r0 + 1] = a1;
                wval_s[r0 + 2] = a2; wval_s[r0 + 3] = a3;
            }
        }
        __syncthreads();
#pragma unroll
        for (int it = 0; it < 2; it++) {
            int i = tid + it * SCAN_THREADS;
            int n = i >> 5, d2 = i & 31;
            float tv = tape_s[n * 33 + d2];
            tape_s[n * 33 + d2] = fmaf(bv_s[n], wval_s[d2] - tv, tv);
        }
        if (tid < SLICE)
            g_hs[((size_t)b * TSTEPS + t) * DDIM + dbase + tid] = hnew_s[tid];
        __syncthreads();
    }

    // ---- final outputs: tape_f and work_f ----
    const size_t TAPE_OFF = (size_t)BATCH * TSTEPS * DDIM;
    const size_t WORK_OFF = TAPE_OFF + (size_t)BATCH * NSLOT * DDIM;
#pragma unroll
    for (int it = 0; it < 2; it++) {
        int i = tid + it * SCAN_THREADS;
        int n = i >> 5, d2 = i & 31;
        dout[TAPE_OFF + ((size_t)b * NSLOT + n) * DDIM + dbase + d2] = tape_s[n * 33 + d2];
    }
    if (tid < SLICE)
        dout[WORK_OFF + (size_t)b * DDIM + dbase + tid] = work_s[dbase + tid];

    cluster_sync_all();   // no CTA exits while peers might still touch its SMEM
}

// ---------------- launcher ----------------
extern "C" void kernel_launch(void* const* d_in, const int* in_sizes, int n_in,
                              void* d_out, int out_size)
{
    const float* x       = (const float*)d_in[0];
    const float* W_in    = (const float*)d_in[1];
    const float* W_out   = (const float*)d_in[2];
    const float* W_h     = (const float*)d_in[3];
    const float* W_x     = (const float*)d_in[4];
    const float* b_h     = (const float*)d_in[5];
    const float* W_write = (const float*)d_in[6];
    float* out = (float*)d_out;

    const int scan_smem = SCAN_SMEM_F * (int)sizeof(float);
    cudaFuncSetAttribute(scan_kernel, cudaFuncAttributeMaxDynamicSharedMemorySize, scan_smem);
    cudaFuncSetAttribute(scan_kernel, cudaFuncAttributeNonPortableClusterSizeAllowed, 1);

    dim3 blk(256);
    sgemm<0><<<dim3(1024 / 128, MROWS / 128), blk>>>(x, W_in, nullptr, MROWS, 1024, DDIM);
    sgemm<1><<<dim3(DDIM / 128, MROWS / 128), blk>>>(nullptr, W_x, nullptr, MROWS, DDIM, DDIM);
    scan_kernel<<<BATCH * CPB, SCAN_THREADS, scan_smem>>>(W_h, W_write, b_h, out);
    sgemm<2><<<dim3(DDIM / 128, MROWS / 128), blk>>>(nullptr, W_out, out, MROWS, DDIM, DDIM);
}

// round 7
// speedup vs baseline: 1.1109x; 1.1109x over previous
#include <cuda_runtime.h>
#include <math.h>
#include <stdint.h>

// ---------------- problem constants ----------------
#define DDIM 512
#define TSTEPS 1024
#define BATCH 8
#define NSLOT 32
#define CPB 8             // CTAs per batch (plain grid, no clusters)
#define SLICE 64          // d-slice per CTA (CPB*SLICE == DDIM)
#define MROWS (BATCH*TSTEPS)
#define SCAN_THREADS 512

// ---------------- static device scratch ----------------
__device__ float g_xproj[(size_t)MROWS * DDIM];
__device__ float g_siluz[(size_t)MROWS * DDIM];
__device__ float g_xw   [(size_t)MROWS * DDIM];
__device__ float g_hs   [(size_t)MROWS * DDIM];

// exchange payloads (parity double-buffered) + monotonic step flags
__device__ float g_hex[BATCH][2][CPB][64];
__device__ float g_wex[BATCH][2][CPB][64];
__device__ int   g_hflag[BATCH][CPB][32];   // use [b][p][0]; 128B padded
__device__ int   g_wflag[BATCH][CPB][32];

__device__ __forceinline__ float siluf(float v) { return v / (1.0f + __expf(-v)); }

__device__ __forceinline__ int ld_acquire_gpu(const int* p) {
    int v;
    asm volatile("ld.acquire.gpu.global.s32 %0, [%1];" : "=r"(v) : "l"(p) : "memory");
    return v;
}
__device__ __forceinline__ void st_release_gpu(int* p, int v) {
    asm volatile("st.release.gpu.global.s32 [%0], %1;" :: "l"(p), "r"(v) : "memory");
}

// ---------------- exact 1.5-entmax over 32 values, one per lane ----------------
// Sort-free rank-based formulation (verified: rel_err 4.5e-7 in R5/R6 runs).
__device__ __forceinline__ float entmax15_warp(float z, int lane) {
    const unsigned F = 0xffffffffu;
    float x0 = 0.5f * z;
    int rank = 0;
#pragma unroll
    for (int j = 0; j < 32; j++) {
        float xj = __shfl_sync(F, x0, j);
        rank += (xj > x0 || (xj == x0 && j < lane)) ? 1 : 0;
    }
    float m = x0;
#pragma unroll
    for (int o = 16; o > 0; o >>= 1) m = fmaxf(m, __shfl_xor_sync(F, m, o));
    float x = x0 - m;
    float s = 0.f, s2 = 0.f, zsv = 0.f;
#pragma unroll
    for (int j = 0; j < 32; j++) {
        float xj = __shfl_sync(F, x, j);
        int   rj = __shfl_sync(F, rank, j);
        if (rj <= lane) { s += xj; s2 += xj * xj; }
        if (rj == lane) zsv = xj;
    }
    float k1     = (float)(lane + 1);
    float mean   = s / k1;
    float meansq = s2 / k1;
    float ss     = k1 * (meansq - mean * mean);
    float delta  = (1.0f - ss) / k1;
    float tau    = mean - sqrtf(fmaxf(delta, 0.0f));
    unsigned bal = __ballot_sync(F, tau <= zsv);
    int support  = __popc(bal) - 1;
    float tau_star = __shfl_sync(F, tau, support);
    float p = fmaxf(x - tau_star, 0.0f);
    return p * p;
}

// ---------------- SGEMM: C[M,N] = A[M,K] @ B[N,K]^T (proven) ----------------
template <int MODE>
__global__ void __launch_bounds__(256)
sgemm(const float* __restrict__ Aext, const float* __restrict__ Bmat,
      float* __restrict__ Cout, int M, int N, int K)
{
    __shared__ float As[8 * 128];
    __shared__ float Bs[8 * 128];

    const int tid = threadIdx.x;
    const int bm = blockIdx.y * 128;
    const int bn = blockIdx.x * 128;
    const int lrow = tid >> 1;
    const int lk   = (tid & 1) * 4;
    const int tx = tid & 15;
    const int ty = tid >> 4;

    const float* A = (MODE == 0) ? Aext : ((MODE == 1) ? g_xproj : g_hs);

    float acc[8][8];
#pragma unroll
    for (int i = 0; i < 8; i++)
#pragma unroll
        for (int j = 0; j < 8; j++) acc[i][j] = 0.0f;

    for (int kt = 0; kt < K; kt += 8) {
        float4 av = *(const float4*)(A + (size_t)(bm + lrow) * K + kt + lk);
        if (MODE == 2) {
            float4 sv = *(const float4*)(g_siluz + (size_t)(bm + lrow) * K + kt + lk);
            av.x *= sv.x; av.y *= sv.y; av.z *= sv.z; av.w *= sv.w;
        }
        As[(lk + 0) * 128 + lrow] = av.x;
        As[(lk + 1) * 128 + lrow] = av.y;
        As[(lk + 2) * 128 + lrow] = av.z;
        As[(lk + 3) * 128 + lrow] = av.w;
        float4 bv = *(const float4*)(Bmat + (size_t)(bn + lrow) * K + kt + lk);
        Bs[(lk + 0) * 128 + lrow] = bv.x;
        Bs[(lk + 1) * 128 + lrow] = bv.y;
        Bs[(lk + 2) * 128 + lrow] = bv.z;
        Bs[(lk + 3) * 128 + lrow] = bv.w;
        __syncthreads();
#pragma unroll
        for (int kk = 0; kk < 8; kk++) {
            float af[8], bf[8];
            *(float4*)(af + 0) = *(const float4*)(As + kk * 128 + ty * 8 + 0);
            *(float4*)(af + 4) = *(const float4*)(As + kk * 128 + ty * 8 + 4);
            *(float4*)(bf + 0) = *(const float4*)(Bs + kk * 128 + tx * 8 + 0);
            *(float4*)(bf + 4) = *(const float4*)(Bs + kk * 128 + tx * 8 + 4);
#pragma unroll
            for (int i = 0; i < 8; i++)
#pragma unroll
                for (int j = 0; j < 8; j++)
                    acc[i][j] = fmaf(af[i], bf[j], acc[i][j]);
        }
        __syncthreads();
    }

#pragma unroll
    for (int i = 0; i < 8; i++) {
        const size_t m = (size_t)(bm + ty * 8 + i);
#pragma unroll
        for (int j = 0; j < 8; j++) {
            const int gn = bn + tx * 8 + j;
            float v = acc[i][j];
            if (MODE == 0) {
                if (gn < DDIM) g_xproj[m * DDIM + gn] = siluf(v);
                else           g_siluz[m * DDIM + (gn - DDIM)] = siluf(v);
            } else if (MODE == 1) {
                g_xw[m * DDIM + gn] = v;
            } else {
                Cout[m * DDIM + gn] = v;
            }
        }
    }
}

// ---------------- init: zero flags (every replay) ----------------
__global__ void init_kernel() {
    int i = blockIdx.x * blockDim.x + threadIdx.x;
    int tot = BATCH * CPB * 32;
    if (i < tot) {
        ((int*)g_hflag)[i] = 0;
        ((int*)g_wflag)[i] = 0;
    }
}

// ---------------- smem layout (float offsets) ----------------
#define WH_F    0                       // 64*512 = 32768
#define TAPE_F  (WH_F + SLICE*DDIM)     // 32*513 = 16416
#define HPRE_F  (TAPE_F + NSLOT*513)    // 512
#define HNEW_F  (HPRE_F + DDIM)         // 512
#define WVAL_F  (HNEW_F + DDIM)         // 512
#define RS_F    (WVAL_F + DDIM)         // 32
#define WS_F    (RS_F + 32)             // 32
#define WVSL_F  (WS_F + 32)             // 64
#define BH_F    (WVSL_F + 64)           // 64
#define XWB_F   (BH_F + 64)             // 128 (parity double buffer)
#define SCAN_SMEM_F (XWB_F + 128)

// ---------------- dual-memory scan: replicated tape, sharded weights ----------------
__global__ void __launch_bounds__(SCAN_THREADS, 1)
scan_kernel(const float* __restrict__ W_h, const float* __restrict__ W_write,
            const float* __restrict__ b_h, float* __restrict__ dout)
{
    extern __shared__ float sm[];
    float* Wh_s   = sm + WH_F;
    float* tape_s = sm + TAPE_F;
    float* hpre_s = sm + HPRE_F;
    float* hnew_s = sm + HNEW_F;
    float* wval_s = sm + WVAL_F;
    float* rs_s   = sm + RS_F;
    float* ws_s   = sm + WS_F;
    float* wvsl_s = sm + WVSL_F;
    float* bh_s   = sm + BH_F;
    float* xwb_s  = sm + XWB_F;

    const int tid  = threadIdx.x;
    const int wid  = tid >> 5;
    const int lane = tid & 31;
    const int b    = blockIdx.x / CPB;
    const int c    = blockIdx.x % CPB;
    const int dbase = c * SLICE;
    const float scale = 0.044194173824159216f;  // 1/sqrt(512)
    const unsigned F = 0xffffffffu;

    // ---- load weight shards ----
    for (int i = tid; i < SLICE * DDIM / 4; i += SCAN_THREADS)
        ((float4*)Wh_s)[i] = ((const float4*)(W_h + (size_t)dbase * DDIM))[i];

    // W_write rows (dbase + wid*4 + 0..3) in registers
    float ww0[16], ww1[16], ww2[16], ww3[16];
    {
        const float* base = W_write + (size_t)(dbase + wid * 4) * DDIM + lane;
#pragma unroll
        for (int kk = 0; kk < 16; kk++) {
            ww0[kk] = base[kk * 32];
            ww1[kk] = base[DDIM + kk * 32];
            ww2[kk] = base[2 * DDIM + kk * 32];
            ww3[kk] = base[3 * DDIM + kk * 32];
        }
    }
    for (int i = tid; i < NSLOT * 513; i += SCAN_THREADS) tape_s[i] = 0.0f;
    hnew_s[tid] = 0.0f;
    if (tid < SLICE) {
        bh_s[tid] = b_h[dbase + tid];
        // xw[1] into parity-1 buffer (consumed at t=0 phase 7)
        xwb_s[64 + tid] = g_xw[((size_t)b * TSTEPS + 1) * DDIM + dbase + tid];
        // h_pre[0] = xw[0] + b_h  (work0 = 0)
        hpre_s[dbase + tid] = g_xw[((size_t)b * TSTEPS) * DDIM + dbase + tid] + bh_s[tid];
    }
    __syncthreads();

    // publish h_pre[0] (slot 0, flag 1)
    if (wid == 15) {
        if (lane < 16) {
            float4 v = *(float4*)&hpre_s[dbase + lane * 4];
            __stcg((float4*)&g_hex[b][0][c][lane * 4], v);
        }
        __threadfence();
        __syncwarp();
        if (lane == 0) st_release_gpu(&g_hflag[b][c][0], 1);
    }

    for (int t = 0; t < TSTEPS; t++) {
        const int par = t & 1;

        // ---- P1: gather h_pre[t] (warps 8..15, one per peer) ----
        if (wid >= 8) {
            int p = wid - 8;
            if (p != c) {
                if (lane == 0) {
                    while (ld_acquire_gpu(&g_hflag[b][p][0]) < t + 1) {}
                }
                __syncwarp();
                if (lane < 16) {
                    float4 v = __ldcg((const float4*)&g_hex[b][par][p][lane * 4]);
                    *(float4*)&hpre_s[p * 64 + lane * 4] = v;
                }
            }
        }
        __syncthreads();

        // ---- P2: r-scores (warp w -> slots 2w, 2w+1) ----
        {
            const int n0 = 2 * wid;
            float r0 = 0.f, r1 = 0.f;
            const float* t0 = &tape_s[n0 * 513];
            const float* t1 = t0 + 513;
#pragma unroll
            for (int kk = 0; kk < 16; kk++) {
                int d = lane + kk * 32;
                float hp = hpre_s[d];
                r0 = fmaf(t0[d], hp, r0);
                r1 = fmaf(t1[d], hp, r1);
            }
#pragma unroll
            for (int o = 16; o > 0; o >>= 1) {
                r0 += __shfl_xor_sync(F, r0, o);
                r1 += __shfl_xor_sync(F, r1, o);
            }
            if (lane == 0) { rs_s[n0] = r0; rs_s[n0 + 1] = r1; }
        }
        __syncthreads();

        // ---- P3: entmax(a) redundantly per warp (no handoff barrier) ----
        float a = entmax15_warp(rs_s[lane] * scale, lane);

        // ---- P4: h_new[d] (thread d) ----
        {
            float rd = 0.f;
#pragma unroll
            for (int n = 0; n < NSLOT; n++)
                rd = fmaf(__shfl_sync(F, a, n), tape_s[n * 513 + tid], rd);
            hnew_s[tid] = tanhf(hpre_s[tid] + rd);
        }
        __syncthreads();

        // ---- P5: w-scores + w_val slice (W_write from registers) ----
        {
            const int n0 = 2 * wid;
            float s0 = 0.f, s1 = 0.f;
            float a0 = 0.f, a1 = 0.f, a2 = 0.f, a3 = 0.f;
            const float* t0 = &tape_s[n0 * 513];
            const float* t1 = t0 + 513;
#pragma unroll
            for (int kk = 0; kk < 16; kk++) {
                int d = lane + kk * 32;
                float hv = hnew_s[d];
                s0 = fmaf(t0[d], hv, s0);
                s1 = fmaf(t1[d], hv, s1);
                a0 = fmaf(ww0[kk], hv, a0);
                a1 = fmaf(ww1[kk], hv, a1);
                a2 = fmaf(ww2[kk], hv, a2);
                a3 = fmaf(ww3[kk], hv, a3);
            }
#pragma unroll
            for (int o = 16; o > 0; o >>= 1) {
                s0 += __shfl_xor_sync(F, s0, o);
                s1 += __shfl_xor_sync(F, s1, o);
                a0 += __shfl_xor_sync(F, a0, o);
                a1 += __shfl_xor_sync(F, a1, o);
                a2 += __shfl_xor_sync(F, a2, o);
                a3 += __shfl_xor_sync(F, a3, o);
            }
            if (lane == 0) {
                ws_s[n0] = s0; ws_s[n0 + 1] = s1;
                wvsl_s[wid * 4 + 0] = a0;
                wvsl_s[wid * 4 + 1] = a1;
                wvsl_s[wid * 4 + 2] = a2;
                wvsl_s[wid * 4 + 3] = a3;
            }
        }
        __syncthreads();

        // ---- P6: publish w_val slice (warp 15); entmax(b) on all warps ----
        if (wid == 15) {
            if (lane < 16) {
                float4 v = *(float4*)&wvsl_s[lane * 4];
                __stcg((float4*)&g_wex[b][par][c][lane * 4], v);
            }
            __threadfence();
            __syncwarp();
            if (lane == 0) st_release_gpu(&g_wflag[b][c][0], t + 1);
        }
        float bb = entmax15_warp(ws_s[lane] * scale, lane);

        // ---- P7: next step's h_pre slice (overlaps exchange 2) ----
        if (t + 1 < TSTEPS) {
            const int r0 = wid * 4;
            float a0 = 0.f, a1 = 0.f, a2 = 0.f, a3 = 0.f;
            const float* w0 = &Wh_s[(r0 + 0) * DDIM];
            const float* w1 = &Wh_s[(r0 + 1) * DDIM];
            const float* w2 = &Wh_s[(r0 + 2) * DDIM];
            const float* w3 = &Wh_s[(r0 + 3) * DDIM];
#pragma unroll
            for (int kk = 0; kk < 16; kk++) {
                int d = lane + kk * 32;
                float hv = hnew_s[d];
                a0 = fmaf(w0[d], hv, a0);
                a1 = fmaf(w1[d], hv, a1);
                a2 = fmaf(w2[d], hv, a2);
                a3 = fmaf(w3[d], hv, a3);
            }
#pragma unroll
            for (int o = 16; o > 0; o >>= 1) {
                a0 += __shfl_xor_sync(F, a0, o);
                a1 += __shfl_xor_sync(F, a1, o);
                a2 += __shfl_xor_sync(F, a2, o);
                a3 += __shfl_xor_sync(F, a3, o);
            }
            if (lane == 0) {
                const float* xwn = &xwb_s[((t + 1) & 1) * 64];
                hpre_s[dbase + r0 + 0] = a0 + xwn[r0 + 0] + bh_s[r0 + 0];
                hpre_s[dbase + r0 + 1] = a1 + xwn[r0 + 1] + bh_s[r0 + 1];
                hpre_s[dbase + r0 + 2] = a2 + xwn[r0 + 2] + bh_s[r0 + 2];
                hpre_s[dbase + r0 + 3] = a3 + xwn[r0 + 3] + bh_s[r0 + 3];
            }
        }
        __syncthreads();
        if (t + 1 < TSTEPS && wid == 15) {
            if (lane < 16) {
                float4 v = *(float4*)&hpre_s[dbase + lane * 4];
                __stcg((float4*)&g_hex[b][(t + 1) & 1][c][lane * 4], v);
            }
            __threadfence();
            __syncwarp();
            if (lane == 0) st_release_gpu(&g_hflag[b][c][0], t + 2);
        }

        // ---- P8: gather w_val; prefetch xw; store g_hs; copy own slice ----
        if (wid >= 8) {
            int p = wid - 8;
            if (p != c) {
                if (lane == 0) {
                    while (ld_acquire_gpu(&g_wflag[b][p][0]) < t + 1) {}
                }
                __syncwarp();
                if (lane < 16) {
                    float4 v = __ldcg((const float4*)&g_wex[b][par][p][lane * 4]);
                    *(float4*)&wval_s[p * 64 + lane * 4] = v;
                }
            }
        } else if (wid < 2) {
            if (t + 2 < TSTEPS)
                xwb_s[(t & 1) * 64 + tid] =
                    g_xw[((size_t)b * TSTEPS + t + 2) * DDIM + dbase + tid];
        } else if (wid == 2 || wid == 3) {
            int j = tid - 64;
            g_hs[((size_t)b * TSTEPS + t) * DDIM + dbase + j] = hnew_s[dbase + j];
        } else if (wid == 4 || wid == 5) {
            int j = tid - 128;
            wval_s[dbase + j] = wvsl_s[j];
        }
        __syncthreads();

        // ---- P9: tape update (thread d) ----
        {
            float wv = wval_s[tid];
#pragma unroll
            for (int n = 0; n < NSLOT; n++) {
                float bn = __shfl_sync(F, bb, n);
                float tv = tape_s[n * 513 + tid];
                tape_s[n * 513 + tid] = fmaf(bn, wv - tv, tv);
            }
        }
        __syncthreads();
    }

    // ---- final outputs: tape_f slice and work_f slice ----
    const size_t TAPE_OFF = (size_t)BATCH * TSTEPS * DDIM;
    const size_t WORK_OFF = TAPE_OFF + (size_t)BATCH * NSLOT * DDIM;
    for (int i = tid; i < NSLOT * SLICE; i += SCAN_THREADS) {
        int n = i >> 6, d2 = i & 63;
        dout[TAPE_OFF + ((size_t)b * NSLOT + n) * DDIM + dbase + d2] =
            tape_s[n * 513 + dbase + d2];
    }
    if (tid < SLICE)
        dout[WORK_OFF + (size_t)b * DDIM + dbase + tid] = hnew_s[dbase + tid];
}

// ---------------- launcher ----------------
extern "C" void kernel_launch(void* const* d_in, const int* in_sizes, int n_in,
                              void* d_out, int out_size)
{
    const float* x       = (const float*)d_in[0];
    const float* W_in    = (const float*)d_in[1];
    const float* W_out   = (const float*)d_in[2];
    const float* W_h     = (const float*)d_in[3];
    const float* W_x     = (const float*)d_in[4];
    const float* b_h     = (const float*)d_in[5];
    const float* W_write = (const float*)d_in[6];
    float* out = (float*)d_out;

    const int scan_smem = SCAN_SMEM_F * (int)sizeof(float);
    cudaFuncSetAttribute(scan_kernel, cudaFuncAttributeMaxDynamicSharedMemorySize, scan_smem);

    dim3 blk(256);
    sgemm<0><<<dim3(1024 / 128, MROWS / 128), blk>>>(x, W_in, nullptr, MROWS, 1024, DDIM);
    sgemm<1><<<dim3(DDIM / 128, MROWS / 128), blk>>>(nullptr, W_x, nullptr, MROWS, DDIM, DDIM);
    init_kernel<<<8, 256>>>();
    scan_kernel<<<BATCH * CPB, SCAN_THREADS, scan_smem>>>(W_h, W_write, b_h, out);
    sgemm<2><<<dim3(DDIM / 128, MROWS / 128), blk>>>(nullptr, W_out, out, MROWS, DDIM, DDIM);
}

// round 8
// speedup vs baseline: 1.1766x; 1.0591x over previous
#include <cuda_runtime.h>
#include <math.h>
#include <stdint.h>

// ---------------- problem constants ----------------
#define DDIM 512
#define TSTEPS 1024
#define BATCH 8
#define NSLOT 32
#define CPB 8             // CTAs per batch (plain grid)
#define SLICE 64          // d-slice per CTA
#define MROWS (BATCH*TSTEPS)
#define SCAN_THREADS 512

// ---------------- static device scratch ----------------
__device__ float g_xproj[(size_t)MROWS * DDIM];
__device__ float g_siluz[(size_t)MROWS * DDIM];
__device__ float g_xw   [(size_t)MROWS * DDIM];
__device__ float g_hs   [(size_t)MROWS * DDIM];

// single combined exchange: [0:64]=h_pre[t] slice, [64:128]=w_val[t-1] slice
__device__ float g_ex[BATCH][2][CPB][128];
__device__ int   g_flag[BATCH][CPB][32];   // use [b][c][0]; 128B padded

__device__ __forceinline__ float siluf(float v) { return v / (1.0f + __expf(-v)); }

__device__ __forceinline__ int ld_acquire_gpu(const int* p) {
    int v;
    asm volatile("ld.acquire.gpu.global.s32 %0, [%1];" : "=r"(v) : "l"(p) : "memory");
    return v;
}
__device__ __forceinline__ void st_release_gpu(int* p, int v) {
    asm volatile("st.release.gpu.global.s32 [%0], %1;" :: "l"(p), "r"(v) : "memory");
}

// ---------------- exact 1.5-entmax over 32 values, one per lane ----------------
__device__ __forceinline__ float entmax15_warp(float z, int lane) {
    const unsigned F = 0xffffffffu;
    float x0 = 0.5f * z;
    int rank = 0;
#pragma unroll
    for (int j = 0; j < 32; j++) {
        float xj = __shfl_sync(F, x0, j);
        rank += (xj > x0 || (xj == x0 && j < lane)) ? 1 : 0;
    }
    float m = x0;
#pragma unroll
    for (int o = 16; o > 0; o >>= 1) m = fmaxf(m, __shfl_xor_sync(F, m, o));
    float x = x0 - m;
    float s = 0.f, s2 = 0.f, zsv = 0.f;
#pragma unroll
    for (int j = 0; j < 32; j++) {
        float xj = __shfl_sync(F, x, j);
        int   rj = __shfl_sync(F, rank, j);
        if (rj <= lane) { s += xj; s2 += xj * xj; }
        if (rj == lane) zsv = xj;
    }
    float k1     = (float)(lane + 1);
    float mean   = s / k1;
    float meansq = s2 / k1;
    float ss     = k1 * (meansq - mean * mean);
    float delta  = (1.0f - ss) / k1;
    float tau    = mean - sqrtf(fmaxf(delta, 0.0f));
    unsigned bal = __ballot_sync(F, tau <= zsv);
    int support  = __popc(bal) - 1;
    float tau_star = __shfl_sync(F, tau, support);
    float p = fmaxf(x - tau_star, 0.0f);
    return p * p;
}

// ---------------- SGEMM: C[M,N] = A[M,K] @ B[N,K]^T (proven) ----------------
template <int MODE>
__global__ void __launch_bounds__(256)
sgemm(const float* __restrict__ Aext, const float* __restrict__ Bmat,
      float* __restrict__ Cout, int M, int N, int K)
{
    __shared__ float As[8 * 128];
    __shared__ float Bs[8 * 128];

    const int tid = threadIdx.x;
    const int bm = blockIdx.y * 128;
    const int bn = blockIdx.x * 128;
    const int lrow = tid >> 1;
    const int lk   = (tid & 1) * 4;
    const int tx = tid & 15;
    const int ty = tid >> 4;

    const float* A = (MODE == 0) ? Aext : ((MODE == 1) ? g_xproj : g_hs);

    float acc[8][8];
#pragma unroll
    for (int i = 0; i < 8; i++)
#pragma unroll
        for (int j = 0; j < 8; j++) acc[i][j] = 0.0f;

    for (int kt = 0; kt < K; kt += 8) {
        float4 av = *(const float4*)(A + (size_t)(bm + lrow) * K + kt + lk);
        if (MODE == 2) {
            float4 sv = *(const float4*)(g_siluz + (size_t)(bm + lrow) * K + kt + lk);
            av.x *= sv.x; av.y *= sv.y; av.z *= sv.z; av.w *= sv.w;
        }
        As[(lk + 0) * 128 + lrow] = av.x;
        As[(lk + 1) * 128 + lrow] = av.y;
        As[(lk + 2) * 128 + lrow] = av.z;
        As[(lk + 3) * 128 + lrow] = av.w;
        float4 bv = *(const float4*)(Bmat + (size_t)(bn + lrow) * K + kt + lk);
        Bs[(lk + 0) * 128 + lrow] = bv.x;
        Bs[(lk + 1) * 128 + lrow] = bv.y;
        Bs[(lk + 2) * 128 + lrow] = bv.z;
        Bs[(lk + 3) * 128 + lrow] = bv.w;
        __syncthreads();
#pragma unroll
        for (int kk = 0; kk < 8; kk++) {
            float af[8], bf[8];
            *(float4*)(af + 0) = *(const float4*)(As + kk * 128 + ty * 8 + 0);
            *(float4*)(af + 4) = *(const float4*)(As + kk * 128 + ty * 8 + 4);
            *(float4*)(bf + 0) = *(const float4*)(Bs + kk * 128 + tx * 8 + 0);
            *(float4*)(bf + 4) = *(const float4*)(Bs + kk * 128 + tx * 8 + 4);
#pragma unroll
            for (int i = 0; i < 8; i++)
#pragma unroll
                for (int j = 0; j < 8; j++)
                    acc[i][j] = fmaf(af[i], bf[j], acc[i][j]);
        }
        __syncthreads();
    }

#pragma unroll
    for (int i = 0; i < 8; i++) {
        const size_t m = (size_t)(bm + ty * 8 + i);
#pragma unroll
        for (int j = 0; j < 8; j++) {
            const int gn = bn + tx * 8 + j;
            float v = acc[i][j];
            if (MODE == 0) {
                if (gn < DDIM) g_xproj[m * DDIM + gn] = siluf(v);
                else           g_siluz[m * DDIM + (gn - DDIM)] = siluf(v);
            } else if (MODE == 1) {
                g_xw[m * DDIM + gn] = v;
            } else {
                Cout[m * DDIM + gn] = v;
            }
        }
    }
}

// ---------------- init: zero flags (every replay) ----------------
__global__ void init_kernel() {
    int i = blockIdx.x * blockDim.x + threadIdx.x;
    if (i < BATCH * CPB * 32) ((int*)g_flag)[i] = 0;
}

// ---------------- smem layout (float offsets) ----------------
#define WH_F    0                       // 64*512 = 32768
#define TAPE_F  (WH_F + SLICE*DDIM)     // 32*513 = 16416
#define HPRE_F  (TAPE_F + NSLOT*513)    // 512
#define HNEW_F  (HPRE_F + DDIM)         // 512
#define WVAL_F  (HNEW_F + DDIM)         // 512
#define RS_F    (WVAL_F + DDIM)         // 32
#define WS_F    (RS_F + 32)             // 32
#define PUB_F   (WS_F + 32)             // 128: [0:64]=hpre_next slice, [64:128]=wval slice
#define BH_F    (PUB_F + 128)           // 64
#define XWB_F   (BH_F + 64)             // 64
#define SCAN_SMEM_F (XWB_F + 64)

// ---------------- dual-memory scan: replicated tape, ONE exchange per step ----------------
__global__ void __launch_bounds__(SCAN_THREADS, 1)
scan_kernel(const float* __restrict__ W_h, const float* __restrict__ W_write,
            const float* __restrict__ b_h, float* __restrict__ dout)
{
    extern __shared__ float sm[];
    float* Wh_s   = sm + WH_F;
    float* tape_s = sm + TAPE_F;
    float* hpre_s = sm + HPRE_F;
    float* hnew_s = sm + HNEW_F;
    float* wval_s = sm + WVAL_F;
    float* rs_s   = sm + RS_F;
    float* ws_s   = sm + WS_F;
    float* pub_s  = sm + PUB_F;
    float* bh_s   = sm + BH_F;
    float* xwb_s  = sm + XWB_F;

    const int tid  = threadIdx.x;
    const int wid  = tid >> 5;
    const int lane = tid & 31;
    const int b    = blockIdx.x / CPB;
    const int c    = blockIdx.x % CPB;
    const int dbase = c * SLICE;
    const float scale = 0.044194173824159216f;  // 1/sqrt(512)
    const unsigned F = 0xffffffffu;

    // ---- weight shards ----
    for (int i = tid; i < SLICE * DDIM / 4; i += SCAN_THREADS)
        ((float4*)Wh_s)[i] = ((const float4*)(W_h + (size_t)dbase * DDIM))[i];

    // W_write rows (dbase + wid*4 + 0..3) in registers
    float ww0[16], ww1[16], ww2[16], ww3[16];
    {
        const float* base = W_write + (size_t)(dbase + wid * 4) * DDIM + lane;
#pragma unroll
        for (int kk = 0; kk < 16; kk++) {
            ww0[kk] = base[kk * 32];
            ww1[kk] = base[DDIM + kk * 32];
            ww2[kk] = base[2 * DDIM + kk * 32];
            ww3[kk] = base[3 * DDIM + kk * 32];
        }
    }
    for (int i = tid; i < NSLOT * 513; i += SCAN_THREADS) tape_s[i] = 0.0f;
    wval_s[tid] = 0.0f;
    // full h_pre[0] = xw[0] + b_h  (work0 = 0): every CTA computes all 512
    hpre_s[tid] = g_xw[((size_t)b * TSTEPS) * DDIM + tid] + b_h[tid];
    if (tid < SLICE) {
        bh_s[tid]  = b_h[dbase + tid];
        xwb_s[tid] = g_xw[((size_t)b * TSTEPS + 1) * DDIM + dbase + tid];
    }
    __syncthreads();

    float bb_prev = 0.0f;   // lane-indexed b[t-1] (per-warp redundant copy)

    for (int t = 0; t < TSTEPS; t++) {
        const int par = t & 1;

        // ---- P0 (t>0): one-shot exchange — publish own {hpre[t], wval[t-1]}
        //      slice, gather peers'; side tasks on free warps ----
        if (t > 0) {
            if (wid >= 8) {
                int p = wid - 8;
                if (p == c) {
                    // publisher: pub_s was finalized last iteration (post-P4 barrier)
                    float4 v = ((const float4*)pub_s)[lane];
                    __stcg((float4*)&g_ex[b][par][c][lane * 4], v);
                    __threadfence();
                    __syncwarp();
                    if (lane == 0) st_release_gpu(&g_flag[b][c][0], t);
                } else {
                    if (lane == 0) {
                        while (ld_acquire_gpu(&g_flag[b][p][0]) < t) {}
                    }
                    __syncwarp();
                    float4 v = __ldcg((const float4*)&g_ex[b][par][p][lane * 4]);
                    int j = lane * 4;
                    if (j < 64) *(float4*)&hpre_s[p * 64 + j]        = v;
                    else        *(float4*)&wval_s[p * 64 + (j - 64)] = v;
                }
            } else if (wid < 4) {
                int j = tid;                      // 0..127: copy own slice
                float v = pub_s[j];
                if (j < 64) hpre_s[dbase + j]        = v;
                else        wval_s[dbase + (j - 64)] = v;
            } else if (wid == 4 || wid == 5) {
                int j = tid - 128;                // prefetch xw[t+1] slice
                if (t + 1 < TSTEPS)
                    xwb_s[j] = g_xw[((size_t)b * TSTEPS + t + 1) * DDIM + dbase + j];
            } else {                              // wid 6,7: store h_new[t-1]
                int j = tid - 192;
                g_hs[((size_t)b * TSTEPS + (t - 1)) * DDIM + dbase + j] = hnew_s[dbase + j];
            }
        }
        __syncthreads();

        // ---- P1: fused deferred tape-update(t-1) + r-scores (warp w: rows 2w,2w+1) ----
        {
            const int n0 = 2 * wid;
            float bb0 = __shfl_sync(F, bb_prev, n0);
            float bb1 = __shfl_sync(F, bb_prev, n0 + 1);
            float r0 = 0.f, r1 = 0.f;
            float* t0 = &tape_s[n0 * 513];
            float* t1 = t0 + 513;
#pragma unroll
            for (int kk = 0; kk < 16; kk++) {
                int d = lane + kk * 32;
                float wv = wval_s[d];
                float hp = hpre_s[d];
                float v0 = t0[d]; v0 = fmaf(bb0, wv - v0, v0); t0[d] = v0; r0 = fmaf(v0, hp, r0);
                float v1 = t1[d]; v1 = fmaf(bb1, wv - v1, v1); t1[d] = v1; r1 = fmaf(v1, hp, r1);
            }
#pragma unroll
            for (int o = 16; o > 0; o >>= 1) {
                r0 += __shfl_xor_sync(F, r0, o);
                r1 += __shfl_xor_sync(F, r1, o);
            }
            if (lane == 0) { rs_s[n0] = r0; rs_s[n0 + 1] = r1; }
        }
        __syncthreads();

        // ---- P2: entmax(a) per warp; read; h_new[tid] ----
        {
            float a = entmax15_warp(rs_s[lane] * scale, lane);
            float rd = 0.f;
#pragma unroll
            for (int n = 0; n < NSLOT; n++)
                rd = fmaf(__shfl_sync(F, a, n), tape_s[n * 513 + tid], rd);
            hnew_s[tid] = tanhf(hpre_s[tid] + rd);
        }
        __syncthreads();

        // ---- P3: w-scores (2 slots/warp) + w_val shard (4 rows/warp, regs) ----
        {
            const int n0 = 2 * wid;
            float s0 = 0.f, s1 = 0.f;
            float a0 = 0.f, a1 = 0.f, a2 = 0.f, a3 = 0.f;
            const float* t0 = &tape_s[n0 * 513];
            const float* t1 = t0 + 513;
#pragma unroll
            for (int kk = 0; kk < 16; kk++) {
                int d = lane + kk * 32;
                float hv = hnew_s[d];
                s0 = fmaf(t0[d], hv, s0);
                s1 = fmaf(t1[d], hv, s1);
                a0 = fmaf(ww0[kk], hv, a0);
                a1 = fmaf(ww1[kk], hv, a1);
                a2 = fmaf(ww2[kk], hv, a2);
                a3 = fmaf(ww3[kk], hv, a3);
            }
#pragma unroll
            for (int o = 16; o > 0; o >>= 1) {
                s0 += __shfl_xor_sync(F, s0, o);
                s1 += __shfl_xor_sync(F, s1, o);
                a0 += __shfl_xor_sync(F, a0, o);
                a1 += __shfl_xor_sync(F, a1, o);
                a2 += __shfl_xor_sync(F, a2, o);
                a3 += __shfl_xor_sync(F, a3, o);
            }
            if (lane == 0) {
                ws_s[n0] = s0; ws_s[n0 + 1] = s1;
                pub_s[64 + wid * 4 + 0] = a0;
                pub_s[64 + wid * 4 + 1] = a1;
                pub_s[64 + wid * 4 + 2] = a2;
                pub_s[64 + wid * 4 + 3] = a3;
            }
        }
        __syncthreads();

        // ---- P4: entmax(b) per warp (becomes bb_prev); W_h matvec -> hpre_next shard ----
        bb_prev = entmax15_warp(ws_s[lane] * scale, lane);
        if (t + 1 < TSTEPS) {
            const int r0 = wid * 4;
            float a0 = 0.f, a1 = 0.f, a2 = 0.f, a3 = 0.f;
            const float* w0 = &Wh_s[(r0 + 0) * DDIM];
            const float* w1 = &Wh_s[(r0 + 1) * DDIM];
            const float* w2 = &Wh_s[(r0 + 2) * DDIM];
            const float* w3 = &Wh_s[(r0 + 3) * DDIM];
#pragma unroll
            for (int kk = 0; kk < 16; kk++) {
                int d = lane + kk * 32;
                float hv = hnew_s[d];
                a0 = fmaf(w0[d], hv, a0);
                a1 = fmaf(w1[d], hv, a1);
                a2 = fmaf(w2[d], hv, a2);
                a3 = fmaf(w3[d], hv, a3);
            }
#pragma unroll
            for (int o = 16; o > 0; o >>= 1) {
                a0 += __shfl_xor_sync(F, a0, o);
                a1 += __shfl_xor_sync(F, a1, o);
                a2 += __shfl_xor_sync(F, a2, o);
                a3 += __shfl_xor_sync(F, a3, o);
            }
            if (lane == 0) {
                pub_s[r0 + 0] = a0 + xwb_s[r0 + 0] + bh_s[r0 + 0];
                pub_s[r0 + 1] = a1 + xwb_s[r0 + 1] + bh_s[r0 + 1];
                pub_s[r0 + 2] = a2 + xwb_s[r0 + 2] + bh_s[r0 + 2];
                pub_s[r0 + 3] = a3 + xwb_s[r0 + 3] + bh_s[r0 + 3];
            }
        }
        __syncthreads();
    }

    // ---- post-loop: final deferred tape update (own cols), outputs ----
    const size_t TAPE_OFF = (size_t)BATCH * TSTEPS * DDIM;
    const size_t WORK_OFF = TAPE_OFF + (size_t)BATCH * NSLOT * DDIM;
    {
        const int n0 = 2 * wid;
        float bb0 = __shfl_sync(F, bb_prev, n0);
        float bb1 = __shfl_sync(F, bb_prev, n0 + 1);
#pragma unroll
        for (int h = 0; h < 2; h++) {
            int j = lane + h * 32;           // 0..63 own-column index
            int d = dbase + j;
            float wv = pub_s[64 + j];        // wval[T-1] own slice (local)
            float v0 = tape_s[n0 * 513 + d];
            float v1 = tape_s[(n0 + 1) * 513 + d];
            v0 = fmaf(bb0, wv - v0, v0);
            v1 = fmaf(bb1, wv - v1, v1);
            dout[TAPE_OFF + ((size_t)b * NSLOT + n0) * DDIM + d]     = v0;
            dout[TAPE_OFF + ((size_t)b * NSLOT + n0 + 1) * DDIM + d] = v1;
        }
    }
    if (tid < SLICE) {
        g_hs[((size_t)b * TSTEPS + TSTEPS - 1) * DDIM + dbase + tid] = hnew_s[dbase + tid];
        dout[WORK_OFF + (size_t)b * DDIM + dbase + tid] = hnew_s[dbase + tid];
    }
}

// ---------------- launcher ----------------
extern "C" void kernel_launch(void* const* d_in, const int* in_sizes, int n_in,
                              void* d_out, int out_size)
{
    const float* x       = (const float*)d_in[0];
    const float* W_in    = (const float*)d_in[1];
    const float* W_out   = (const float*)d_in[2];
    const float* W_h     = (const float*)d_in[3];
    const float* W_x     = (const float*)d_in[4];
    const float* b_h     = (const float*)d_in[5];
    const float* W_write = (const float*)d_in[6];
    float* out = (float*)d_out;

    const int scan_smem = SCAN_SMEM_F * (int)sizeof(float);
    cudaFuncSetAttribute(scan_kernel, cudaFuncAttributeMaxDynamicSharedMemorySize, scan_smem);

    dim3 blk(256);
    sgemm<0><<<dim3(1024 / 128, MROWS / 128), blk>>>(x, W_in, nullptr, MROWS, 1024, DDIM);
    sgemm<1><<<dim3(DDIM / 128, MROWS / 128), blk>>>(nullptr, W_x, nullptr, MROWS, DDIM, DDIM);
    init_kernel<<<8, 256>>>();
    scan_kernel<<<BATCH * CPB, SCAN_THREADS, scan_smem>>>(W_h, W_write, b_h, out);
    sgemm<2><<<dim3(DDIM / 128, MROWS / 128), blk>>>(nullptr, W_out, out, MROWS, DDIM, DDIM);
}

// round 9
// speedup vs baseline: 1.3336x; 1.1334x over previous
#include <cuda_runtime.h>
#include <math.h>
#include <stdint.h>

// ---------------- problem constants ----------------
#define DDIM 512
#define TSTEPS 1024
#define BATCH 8
#define NSLOT 32
#define CPB 8             // CTAs per batch (plain grid)
#define SLICE 64          // d-slice per CTA
#define MROWS (BATCH*TSTEPS)
#define SCAN_THREADS 512

// ---------------- static device scratch ----------------
__device__ float g_xproj[(size_t)MROWS * DDIM];
__device__ float g_siluz[(size_t)MROWS * DDIM];
__device__ float g_xw   [(size_t)MROWS * DDIM];
__device__ float g_hs   [(size_t)MROWS * DDIM];

// single combined exchange: [0:64]=h_pre[t] slice, [64:128]=w_val[t-1] slice
__device__ float g_ex[BATCH][2][CPB][128];
__device__ int   g_flag[BATCH][CPB][32];   // use [b][c][0]; 128B padded

__device__ __forceinline__ float siluf(float v) { return v / (1.0f + __expf(-v)); }

__device__ __forceinline__ int ld_acquire_gpu(const int* p) {
    int v;
    asm volatile("ld.acquire.gpu.global.s32 %0, [%1];" : "=r"(v) : "l"(p) : "memory");
    return v;
}
__device__ __forceinline__ void st_release_gpu(int* p, int v) {
    asm volatile("st.release.gpu.global.s32 [%0], %1;" :: "l"(p), "r"(v) : "memory");
}

// ---------------- exact 1.5-entmax over 32 values, one per lane ----------------
// (proven: rel_err 4.456e-7). Now executed by ONE warp only.
__device__ __forceinline__ float entmax15_warp(float z, int lane) {
    const unsigned F = 0xffffffffu;
    float x0 = 0.5f * z;
    int rank = 0;
#pragma unroll
    for (int j = 0; j < 32; j++) {
        float xj = __shfl_sync(F, x0, j);
        rank += (xj > x0 || (xj == x0 && j < lane)) ? 1 : 0;
    }
    float m = x0;
#pragma unroll
    for (int o = 16; o > 0; o >>= 1) m = fmaxf(m, __shfl_xor_sync(F, m, o));
    float x = x0 - m;
    float s = 0.f, s2 = 0.f, zsv = 0.f;
#pragma unroll
    for (int j = 0; j < 32; j++) {
        float xj = __shfl_sync(F, x, j);
        int   rj = __shfl_sync(F, rank, j);
        if (rj <= lane) { s += xj; s2 += xj * xj; }
        if (rj == lane) zsv = xj;
    }
    float k1     = (float)(lane + 1);
    float mean   = s / k1;
    float meansq = s2 / k1;
    float ss     = k1 * (meansq - mean * mean);
    float delta  = (1.0f - ss) / k1;
    float tau    = mean - sqrtf(fmaxf(delta, 0.0f));
    unsigned bal = __ballot_sync(F, tau <= zsv);
    int support  = __popc(bal) - 1;
    float tau_star = __shfl_sync(F, tau, support);
    float p = fmaxf(x - tau_star, 0.0f);
    return p * p;
}

// ---------------- SGEMM: C[M,N] = A[M,K] @ B[N,K]^T (proven) ----------------
template <int MODE>
__global__ void __launch_bounds__(256)
sgemm(const float* __restrict__ Aext, const float* __restrict__ Bmat,
      float* __restrict__ Cout, int M, int N, int K)
{
    __shared__ float As[8 * 128];
    __shared__ float Bs[8 * 128];

    const int tid = threadIdx.x;
    const int bm = blockIdx.y * 128;
    const int bn = blockIdx.x * 128;
    const int lrow = tid >> 1;
    const int lk   = (tid & 1) * 4;
    const int tx = tid & 15;
    const int ty = tid >> 4;

    const float* A = (MODE == 0) ? Aext : ((MODE == 1) ? g_xproj : g_hs);

    float acc[8][8];
#pragma unroll
    for (int i = 0; i < 8; i++)
#pragma unroll
        for (int j = 0; j < 8; j++) acc[i][j] = 0.0f;

    for (int kt = 0; kt < K; kt += 8) {
        float4 av = *(const float4*)(A + (size_t)(bm + lrow) * K + kt + lk);
        if (MODE == 2) {
            float4 sv = *(const float4*)(g_siluz + (size_t)(bm + lrow) * K + kt + lk);
            av.x *= sv.x; av.y *= sv.y; av.z *= sv.z; av.w *= sv.w;
        }
        As[(lk + 0) * 128 + lrow] = av.x;
        As[(lk + 1) * 128 + lrow] = av.y;
        As[(lk + 2) * 128 + lrow] = av.z;
        As[(lk + 3) * 128 + lrow] = av.w;
        float4 bv = *(const float4*)(Bmat + (size_t)(bn + lrow) * K + kt + lk);
        Bs[(lk + 0) * 128 + lrow] = bv.x;
        Bs[(lk + 1) * 128 + lrow] = bv.y;
        Bs[(lk + 2) * 128 + lrow] = bv.z;
        Bs[(lk + 3) * 128 + lrow] = bv.w;
        __syncthreads();
#pragma unroll
        for (int kk = 0; kk < 8; kk++) {
            float af[8], bf[8];
            *(float4*)(af + 0) = *(const float4*)(As + kk * 128 + ty * 8 + 0);
            *(float4*)(af + 4) = *(const float4*)(As + kk * 128 + ty * 8 + 4);
            *(float4*)(bf + 0) = *(const float4*)(Bs + kk * 128 + tx * 8 + 0);
            *(float4*)(bf + 4) = *(const float4*)(Bs + kk * 128 + tx * 8 + 4);
#pragma unroll
            for (int i = 0; i < 8; i++)
#pragma unroll
                for (int j = 0; j < 8; j++)
                    acc[i][j] = fmaf(af[i], bf[j], acc[i][j]);
        }
        __syncthreads();
    }

#pragma unroll
    for (int i = 0; i < 8; i++) {
        const size_t m = (size_t)(bm + ty * 8 + i);
#pragma unroll
        for (int j = 0; j < 8; j++) {
            const int gn = bn + tx * 8 + j;
            float v = acc[i][j];
            if (MODE == 0) {
                if (gn < DDIM) g_xproj[m * DDIM + gn] = siluf(v);
                else           g_siluz[m * DDIM + (gn - DDIM)] = siluf(v);
            } else if (MODE == 1) {
                g_xw[m * DDIM + gn] = v;
            } else {
                Cout[m * DDIM + gn] = v;
            }
        }
    }
}

// ---------------- init: zero flags (every replay) ----------------
__global__ void init_kernel() {
    int i = blockIdx.x * blockDim.x + threadIdx.x;
    if (i < BATCH * CPB * 32) ((int*)g_flag)[i] = 0;
}

// ---------------- smem layout (float offsets) ----------------
#define WH_F    0                       // 64*512 = 32768
#define TAPE_F  (WH_F + SLICE*DDIM)     // 32*513 = 16416
#define HPRE_F  (TAPE_F + NSLOT*513)    // 512
#define HNEW_F  (HPRE_F + DDIM)         // 512
#define WVAL_F  (HNEW_F + DDIM)         // 512
#define RS_F    (WVAL_F + DDIM)         // 32
#define WS_F    (RS_F + 32)             // 32
#define AS_F    (WS_F + 32)             // 32  entmax(a) result
#define BVS_F   (AS_F + 32)             // 32  entmax(b) result
#define PUB_F   (BVS_F + 32)            // 128: [0:64]=hpre_next slice, [64:128]=wval slice
#define BH_F    (PUB_F + 128)           // 64
#define XWB_F   (BH_F + 64)             // 64
#define SCAN_SMEM_F (XWB_F + 64)

// ---------------- dual-memory scan: replicated tape, one exchange/step,
//                   single-warp entmax + smem broadcast ----------------
__global__ void __launch_bounds__(SCAN_THREADS, 1)
scan_kernel(const float* __restrict__ W_h, const float* __restrict__ W_write,
            const float* __restrict__ b_h, float* __restrict__ dout)
{
    extern __shared__ float sm[];
    float* Wh_s   = sm + WH_F;
    float* tape_s = sm + TAPE_F;
    float* hpre_s = sm + HPRE_F;
    float* hnew_s = sm + HNEW_F;
    float* wval_s = sm + WVAL_F;
    float* rs_s   = sm + RS_F;
    float* ws_s   = sm + WS_F;
    float* a_s    = sm + AS_F;
    float* bv_s   = sm + BVS_F;
    float* pub_s  = sm + PUB_F;
    float* bh_s   = sm + BH_F;
    float* xwb_s  = sm + XWB_F;

    const int tid  = threadIdx.x;
    const int wid  = tid >> 5;
    const int lane = tid & 31;
    const int b    = blockIdx.x / CPB;
    const int c    = blockIdx.x % CPB;
    const int dbase = c * SLICE;
    const float scale = 0.044194173824159216f;  // 1/sqrt(512)
    const unsigned F = 0xffffffffu;

    // ---- weight shards ----
    for (int i = tid; i < SLICE * DDIM / 4; i += SCAN_THREADS)
        ((float4*)Wh_s)[i] = ((const float4*)(W_h + (size_t)dbase * DDIM))[i];

    // W_write rows (dbase + wid*4 + 0..3) in registers
    float ww0[16], ww1[16], ww2[16], ww3[16];
    {
        const float* base = W_write + (size_t)(dbase + wid * 4) * DDIM + lane;
#pragma unroll
        for (int kk = 0; kk < 16; kk++) {
            ww0[kk] = base[kk * 32];
            ww1[kk] = base[DDIM + kk * 32];
            ww2[kk] = base[2 * DDIM + kk * 32];
            ww3[kk] = base[3 * DDIM + kk * 32];
        }
    }
    for (int i = tid; i < NSLOT * 513; i += SCAN_THREADS) tape_s[i] = 0.0f;
    wval_s[tid] = 0.0f;
    // full h_pre[0] = xw[0] + b_h  (work0 = 0)
    hpre_s[tid] = g_xw[((size_t)b * TSTEPS) * DDIM + tid] + b_h[tid];
    if (tid < SLICE) {
        bh_s[tid]  = b_h[dbase + tid];
        xwb_s[tid] = g_xw[((size_t)b * TSTEPS + 1) * DDIM + dbase + tid];
    }
    if (tid < NSLOT) bv_s[tid] = 0.0f;   // b[-1] = 0 -> first tape update no-op
    __syncthreads();

    for (int t = 0; t < TSTEPS; t++) {
        const int par = t & 1;

        // ---- P0 (t>0): one-shot exchange; side tasks on free warps ----
        if (t > 0) {
            if (wid >= 8) {
                int p = wid - 8;
                if (p == c) {
                    float4 v = ((const float4*)pub_s)[lane];
                    __stcg((float4*)&g_ex[b][par][c][lane * 4], v);
                    __threadfence();
                    __syncwarp();
                    if (lane == 0) st_release_gpu(&g_flag[b][c][0], t);
                } else {
                    if (lane == 0) {
                        while (ld_acquire_gpu(&g_flag[b][p][0]) < t) {}
                    }
                    __syncwarp();
                    float4 v = __ldcg((const float4*)&g_ex[b][par][p][lane * 4]);
                    int j = lane * 4;
                    if (j < 64) *(float4*)&hpre_s[p * 64 + j]        = v;
                    else        *(float4*)&wval_s[p * 64 + (j - 64)] = v;
                }
            } else if (wid < 4) {
                int j = tid;                      // 0..127: copy own slice
                float v = pub_s[j];
                if (j < 64) hpre_s[dbase + j]        = v;
                else        wval_s[dbase + (j - 64)] = v;
            } else if (wid == 4 || wid == 5) {
                int j = tid - 128;                // prefetch xw[t+1] slice
                if (t + 1 < TSTEPS)
                    xwb_s[j] = g_xw[((size_t)b * TSTEPS + t + 1) * DDIM + dbase + j];
            } else {                              // wid 6,7: store h_new[t-1]
                int j = tid - 192;
                g_hs[((size_t)b * TSTEPS + (t - 1)) * DDIM + dbase + j] = hnew_s[dbase + j];
            }
        }
        __syncthreads();

        // ---- P1: fused deferred tape-update(t-1) + r-scores (warp w: rows 2w,2w+1) ----
        {
            const int n0 = 2 * wid;
            float bb0 = bv_s[n0];        // broadcast LDS
            float bb1 = bv_s[n0 + 1];
            float r0 = 0.f, r1 = 0.f;
            float* t0 = &tape_s[n0 * 513];
            float* t1 = t0 + 513;
#pragma unroll
            for (int kk = 0; kk < 16; kk++) {
                int d = lane + kk * 32;
                float wv = wval_s[d];
                float hp = hpre_s[d];
                float v0 = t0[d]; v0 = fmaf(bb0, wv - v0, v0); t0[d] = v0; r0 = fmaf(v0, hp, r0);
                float v1 = t1[d]; v1 = fmaf(bb1, wv - v1, v1); t1[d] = v1; r1 = fmaf(v1, hp, r1);
            }
#pragma unroll
            for (int o = 16; o > 0; o >>= 1) {
                r0 += __shfl_xor_sync(F, r0, o);
                r1 += __shfl_xor_sync(F, r1, o);
            }
            if (lane == 0) { rs_s[n0] = r0; rs_s[n0 + 1] = r1; }
        }
        __syncthreads();

        // ---- P2: entmax(a) on warp 0 ONLY -> a_s ----
        if (wid == 0) {
            float a = entmax15_warp(rs_s[lane] * scale, lane);
            a_s[lane] = a;
        }
        __syncthreads();

        // ---- P3: h_new[tid] = tanh(hpre + sum_n a_s[n]*tape[n][tid]) ----
        {
            float rd = 0.f;
#pragma unroll
            for (int n = 0; n < NSLOT; n++)
                rd = fmaf(a_s[n], tape_s[n * 513 + tid], rd);
            hnew_s[tid] = tanhf(hpre_s[tid] + rd);
        }
        __syncthreads();

        // ---- P4: w-scores (2 slots/warp) + w_val shard (4 rows/warp, regs) ----
        {
            const int n0 = 2 * wid;
            float s0 = 0.f, s1 = 0.f;
            float a0 = 0.f, a1 = 0.f, a2 = 0.f, a3 = 0.f;
            const float* t0 = &tape_s[n0 * 513];
            const float* t1 = t0 + 513;
#pragma unroll
            for (int kk = 0; kk < 16; kk++) {
                int d = lane + kk * 32;
                float hv = hnew_s[d];
                s0 = fmaf(t0[d], hv, s0);
                s1 = fmaf(t1[d], hv, s1);
                a0 = fmaf(ww0[kk], hv, a0);
                a1 = fmaf(ww1[kk], hv, a1);
                a2 = fmaf(ww2[kk], hv, a2);
                a3 = fmaf(ww3[kk], hv, a3);
            }
#pragma unroll
            for (int o = 16; o > 0; o >>= 1) {
                s0 += __shfl_xor_sync(F, s0, o);
                s1 += __shfl_xor_sync(F, s1, o);
                a0 += __shfl_xor_sync(F, a0, o);
                a1 += __shfl_xor_sync(F, a1, o);
                a2 += __shfl_xor_sync(F, a2, o);
                a3 += __shfl_xor_sync(F, a3, o);
            }
            if (lane == 0) {
                ws_s[n0] = s0; ws_s[n0 + 1] = s1;
                pub_s[64 + wid * 4 + 0] = a0;
                pub_s[64 + wid * 4 + 1] = a1;
                pub_s[64 + wid * 4 + 2] = a2;
                pub_s[64 + wid * 4 + 3] = a3;
            }
        }
        __syncthreads();

        // ---- P5: entmax(b) on warp 0 -> bv_s; all warps W_h matvec -> pub_s[0:64] ----
        if (wid == 0) {
            float bb = entmax15_warp(ws_s[lane] * scale, lane);
            bv_s[lane] = bb;
        }
        if (t + 1 < TSTEPS) {
            const int r0 = wid * 4;
            float a0 = 0.f, a1 = 0.f, a2 = 0.f, a3 = 0.f;
            const float* w0 = &Wh_s[(r0 + 0) * DDIM];
            const float* w1 = &Wh_s[(r0 + 1) * DDIM];
            const float* w2 = &Wh_s[(r0 + 2) * DDIM];
            const float* w3 = &Wh_s[(r0 + 3) * DDIM];
#pragma unroll
            for (int kk = 0; kk < 16; kk++) {
                int d = lane + kk * 32;
                float hv = hnew_s[d];
                a0 = fmaf(w0[d], hv, a0);
                a1 = fmaf(w1[d], hv, a1);
                a2 = fmaf(w2[d], hv, a2);
                a3 = fmaf(w3[d], hv, a3);
            }
#pragma unroll
            for (int o = 16; o > 0; o >>= 1) {
                a0 += __shfl_xor_sync(F, a0, o);
                a1 += __shfl_xor_sync(F, a1, o);
                a2 += __shfl_xor_sync(F, a2, o);
                a3 += __shfl_xor_sync(F, a3, o);
            }
            if (lane == 0) {
                pub_s[r0 + 0] = a0 + xwb_s[r0 + 0] + bh_s[r0 + 0];
                pub_s[r0 + 1] = a1 + xwb_s[r0 + 1] + bh_s[r0 + 1];
                pub_s[r0 + 2] = a2 + xwb_s[r0 + 2] + bh_s[r0 + 2];
                pub_s[r0 + 3] = a3 + xwb_s[r0 + 3] + bh_s[r0 + 3];
            }
        }
        __syncthreads();
    }

    // ---- post-loop: final deferred tape update (own cols), outputs ----
    const size_t TAPE_OFF = (size_t)BATCH * TSTEPS * DDIM;
    const size_t WORK_OFF = TAPE_OFF + (size_t)BATCH * NSLOT * DDIM;
    {
        const int n0 = 2 * wid;
        float bb0 = bv_s[n0];
        float bb1 = bv_s[n0 + 1];
#pragma unroll
        for (int h = 0; h < 2; h++) {
            int j = lane + h * 32;           // 0..63 own-column index
            int d = dbase + j;
            float wv = pub_s[64 + j];        // wval[T-1] own slice (local)
            float v0 = tape_s[n0 * 513 + d];
            float v1 = tape_s[(n0 + 1) * 513 + d];
            v0 = fmaf(bb0, wv - v0, v0);
            v1 = fmaf(bb1, wv - v1, v1);
            dout[TAPE_OFF + ((size_t)b * NSLOT + n0) * DDIM + d]     = v0;
            dout[TAPE_OFF + ((size_t)b * NSLOT + n0 + 1) * DDIM + d] = v1;
        }
    }
    if (tid < SLICE) {
        g_hs[((size_t)b * TSTEPS + TSTEPS - 1) * DDIM + dbase + tid] = hnew_s[dbase + tid];
        dout[WORK_OFF + (size_t)b * DDIM + dbase + tid] = hnew_s[dbase + tid];
    }
}

// ---------------- launcher ----------------
extern "C" void kernel_launch(void* const* d_in, const int* in_sizes, int n_in,
                              void* d_out, int out_size)
{
    const float* x       = (const float*)d_in[0];
    const float* W_in    = (const float*)d_in[1];
    const float* W_out   = (const float*)d_in[2];
    const float* W_h     = (const float*)d_in[3];
    const float* W_x     = (const float*)d_in[4];
    const float* b_h     = (const float*)d_in[5];
    const float* W_write = (const float*)d_in[6];
    float* out = (float*)d_out;

    const int scan_smem = SCAN_SMEM_F * (int)sizeof(float);
    cudaFuncSetAttribute(scan_kernel, cudaFuncAttributeMaxDynamicSharedMemorySize, scan_smem);

    dim3 blk(256);
    sgemm<0><<<dim3(1024 / 128, MROWS / 128), blk>>>(x, W_in, nullptr, MROWS, 1024, DDIM);
    sgemm<1><<<dim3(DDIM / 128, MROWS / 128), blk>>>(nullptr, W_x, nullptr, MROWS, DDIM, DDIM);
    init_kernel<<<8, 256>>>();
    scan_kernel<<<BATCH * CPB, SCAN_THREADS, scan_smem>>>(W_h, W_write, b_h, out);
    sgemm<2><<<dim3(DDIM / 128, MROWS / 128), blk>>>(nullptr, W_out, out, MROWS, DDIM, DDIM);
}